// round 17
// baseline (speedup 1.0000x reference)
#include <cuda_runtime.h>
#include <stdint.h>

#define NB 4
#define SEQ 2048
#define CH 512
#define NH 8
#define HD 64
// SCALE * log2(e)
#define SC2 0.18033688011112042f

// ---------------- device scratch (allocation-free rule: static globals) ----------------
__device__ uint32_t g_Q[(size_t)NB * NH * SEQ * HD];
__device__ uint32_t g_K[(size_t)NB * NH * SEQ * HD];
__device__ uint32_t g_V[(size_t)NB * NH * SEQ * HD];
__device__ float    g_oA[(size_t)NB * SEQ * CH];     // split-0 unnormalized O
__device__ float    g_oB[(size_t)NB * SEQ * CH];     // split-1 unnormalized O
__device__ float    g_l[(size_t)2 * NB * NH * SEQ];  // split row sums

// ---------------- stream/event pool for forked graph capture ---------------------------
static cudaStream_t g_str[NB];
static cudaEvent_t  g_fork, g_join[NB];
static struct StreamPool {
    StreamPool() {
        for (int i = 0; i < NB; i++) {
            cudaStreamCreateWithFlags(&g_str[i], cudaStreamNonBlocking);
            cudaEventCreateWithFlags(&g_join[i], cudaEventDisableTiming);
        }
        cudaEventCreateWithFlags(&g_fork, cudaEventDisableTiming);
    }
} g_pool;

// ---------------- helpers ---------------------------------------------------------------
__device__ __forceinline__ uint32_t f2tf(float f) {
    uint32_t r;
    asm("cvt.rna.tf32.f32 %0, %1;" : "=r"(r) : "f"(f));
    return r;
}

__device__ __forceinline__ float ex2(float x) {
    float r;
    asm("ex2.approx.ftz.f32 %0, %1;" : "=f"(r) : "f"(x));
    return r;
}

__device__ __forceinline__ float frcp(float x) {
    float r;
    asm("rcp.approx.ftz.f32 %0, %1;" : "=f"(r) : "f"(x));
    return r;
}

__device__ __forceinline__ void mma8(float& d0, float& d1, float& d2, float& d3,
                                     uint32_t a0, uint32_t a1, uint32_t a2, uint32_t a3,
                                     uint32_t b0, uint32_t b1) {
    asm volatile(
        "mma.sync.aligned.m16n8k8.row.col.f32.tf32.tf32.f32 "
        "{%0,%1,%2,%3},{%4,%5,%6,%7},{%8,%9},{%0,%1,%2,%3};"
        : "+f"(d0), "+f"(d1), "+f"(d2), "+f"(d3)
        : "r"(a0), "r"(a1), "r"(a2), "r"(a3), "r"(b0), "r"(b1));
}

// ---------------- JAX threefry2x32, partitionable: bits for flat index ------------------
__device__ __forceinline__ uint32_t tf_bits(uint32_t idx) {
    const uint32_t ks0 = 0u, ks1 = 42u, ks2 = 0x1BD11BF0u;
    uint32_t x0 = ks0;
    uint32_t x1 = idx + ks1;
#define TF_R(r) { x0 += x1; x1 = __funnelshift_l(x1, x1, (r)); x1 ^= x0; }
    TF_R(13) TF_R(15) TF_R(26) TF_R(6)   x0 += ks1; x1 += ks2 + 1u;
    TF_R(17) TF_R(29) TF_R(16) TF_R(24)  x0 += ks2; x1 += ks0 + 2u;
    TF_R(13) TF_R(15) TF_R(26) TF_R(6)   x0 += ks0; x1 += ks1 + 3u;
    TF_R(17) TF_R(29) TF_R(16) TF_R(24)  x0 += ks1; x1 += ks2 + 4u;
    TF_R(13) TF_R(15) TF_R(26) TF_R(6)   x0 += ks2; x1 += ks0 + 5u;
#undef TF_R
    return x0 ^ x1;
}

// ---------------- hybrid -log(u): MUFU lg2 fast path + exact series near u->1 ----------
__device__ __forceinline__ float neglog_u(uint32_t bits) {
    float v = __uint_as_float((bits >> 9) | 0x3f800000u);  // [1,2)
    float u = v - 1.0f;                                    // exact
    float l;
    asm("lg2.approx.ftz.f32 %0, %1;" : "=f"(l) : "f"(u));
    float t1 = -0.6931471805599453f * l;
    float d = 2.0f - v;                                    // = 1-u, exact
    float t2 = d * fmaf(d, fmaf(d, 0.3333333333f, 0.5f), 1.0f);
    return (d < 0.0078125f) ? t2 : t1;
}

// ---------------- QKV projection GEMM: 128x128 tile, BK=32 (proven R8/R14 shape) -------
__global__ __launch_bounds__(256, 2) void proj_qkv(
    const float* __restrict__ x, const float* __restrict__ y, const float* __restrict__ z,
    const float* __restrict__ Wq, const float* __restrict__ bq,
    const float* __restrict__ Wk, const float* __restrict__ bk,
    const float* __restrict__ Wv, const float* __restrict__ bv,
    uint32_t* __restrict__ oq, uint32_t* __restrict__ ok, uint32_t* __restrict__ ov,
    int bi)
{
    __shared__ uint32_t As[128 * 36];
    __shared__ uint32_t Ws[128 * 36];
    const int which = blockIdx.z;
    const float* X    = (which == 0) ? x  : (which == 1) ? y  : z;
    const float* W    = (which == 0) ? Wq : (which == 1) ? Wk : Wv;
    const float* bias = (which == 0) ? bq : (which == 1) ? bk : bv;
    uint32_t* out     = (which == 0) ? oq : (which == 1) ? ok : ov;

    const int n0 = blockIdx.x * 128;
    const int j0 = blockIdx.y * 128;
    const int t  = threadIdx.x;
    const int w  = t >> 5, lane = t & 31;
    const int wm = w & 1, wn = w >> 1;
    const int g  = lane >> 2, tig = lane & 3;
    const float* Xb = X + (size_t)bi * SEQ * CH;

    float acc[4][4][4] = {};

    float4 pa[4], pw[4];
    #pragma unroll
    for (int p = 0; p < 4; p++) {
        int i = p * 256 + t; int r = i >> 3; int c4 = (i & 7) * 4;
        pa[p] = *(const float4*)&Xb[(size_t)(n0 + r) * CH + c4];
        pw[p] = *(const float4*)&W[(size_t)(j0 + r) * CH + c4];
    }

    for (int k0 = 0; k0 < CH; k0 += 32) {
        __syncthreads();
        #pragma unroll
        for (int p = 0; p < 4; p++) {
            int i = p * 256 + t; int r = i >> 3; int c4 = (i & 7) * 4;
            As[r * 36 + c4 + 0] = f2tf(pa[p].x);
            As[r * 36 + c4 + 1] = f2tf(pa[p].y);
            As[r * 36 + c4 + 2] = f2tf(pa[p].z);
            As[r * 36 + c4 + 3] = f2tf(pa[p].w);
            Ws[r * 36 + c4 + 0] = f2tf(pw[p].x);
            Ws[r * 36 + c4 + 1] = f2tf(pw[p].y);
            Ws[r * 36 + c4 + 2] = f2tf(pw[p].z);
            Ws[r * 36 + c4 + 3] = f2tf(pw[p].w);
        }
        __syncthreads();
        if (k0 + 32 < CH) {
            #pragma unroll
            for (int p = 0; p < 4; p++) {
                int i = p * 256 + t; int r = i >> 3; int c4 = (i & 7) * 4;
                pa[p] = *(const float4*)&Xb[(size_t)(n0 + r) * CH + k0 + 32 + c4];
                pw[p] = *(const float4*)&W[(size_t)(j0 + r) * CH + k0 + 32 + c4];
            }
        }
        #pragma unroll
        for (int ks = 0; ks < 4; ks++) {
            const int kb = ks * 8;
            uint32_t af[4][4], bf[4][2];
            #pragma unroll
            for (int mt = 0; mt < 4; mt++) {
                int m = wm * 64 + mt * 16;
                af[mt][0] = As[(m + g) * 36 + kb + tig];
                af[mt][1] = As[(m + g + 8) * 36 + kb + tig];
                af[mt][2] = As[(m + g) * 36 + kb + tig + 4];
                af[mt][3] = As[(m + g + 8) * 36 + kb + tig + 4];
            }
            #pragma unroll
            for (int nt = 0; nt < 4; nt++) {
                int n = wn * 32 + nt * 8;
                bf[nt][0] = Ws[(n + g) * 36 + kb + tig];
                bf[nt][1] = Ws[(n + g) * 36 + kb + tig + 4];
            }
            #pragma unroll
            for (int mt = 0; mt < 4; mt++)
                #pragma unroll
                for (int nt = 0; nt < 4; nt++)
                    mma8(acc[mt][nt][0], acc[mt][nt][1], acc[mt][nt][2], acc[mt][nt][3],
                         af[mt][0], af[mt][1], af[mt][2], af[mt][3],
                         bf[nt][0], bf[nt][1]);
        }
    }

    #pragma unroll
    for (int mt = 0; mt < 4; mt++) {
        int n = n0 + wm * 64 + mt * 16 + g;
        #pragma unroll
        for (int nt = 0; nt < 4; nt++) {
            int j = j0 + wn * 32 + nt * 8 + 2 * tig;
            float2 bj = *(const float2*)&bias[j];
            uint2 v0 = make_uint2(f2tf(acc[mt][nt][0] + bj.x), f2tf(acc[mt][nt][1] + bj.y));
            uint2 v1 = make_uint2(f2tf(acc[mt][nt][2] + bj.x), f2tf(acc[mt][nt][3] + bj.y));
            size_t base = (((size_t)bi * NH + (j >> 6)) * SEQ) * HD + (j & 63);
            *(uint2*)&out[base + (size_t)n * HD]       = v0;
            *(uint2*)&out[base + (size_t)(n + 8) * HD] = v1;
        }
    }
}

// ---------------- output projection 64x64 with fused split-combine ---------------------
// linv[row][head] = 1/(l0+l1) computed ONCE into 2KB smem; A-staging reads both split
// buffers and stages (O0+O1)*linv as tf32 — bit-identical to combine+proj, and the
// combine kernel plus its dependency bubble disappear from each chain's tail.
__global__ __launch_bounds__(256, 3) void proj_out64_fused(
    const float* __restrict__ O0, const float* __restrict__ O1,
    const float* __restrict__ lbuf, const float* __restrict__ W,
    const float* __restrict__ bias, float* __restrict__ out, int bi)
{
    __shared__ uint32_t As[64 * 36];
    __shared__ uint32_t Ws[64 * 36];
    __shared__ float    linv[64 * 8];      // [row][head]
    const int n0 = blockIdx.x * 64;
    const int j0 = blockIdx.y * 64;
    const int t  = threadIdx.x;
    const int w  = t >> 5, lane = t & 31;
    const int wm = w & 1, wn = w >> 1;      // 2(m) x 4(n); warp tile 32x16
    const int g  = lane >> 2, tig = lane & 3;
    const size_t LS = (size_t)NB * NH * SEQ;

    // one-time: row-sum inverses for this 64-row tile (all 8 heads)
    #pragma unroll
    for (int q = 0; q < 2; q++) {
        int i = q * 256 + t;               // i = r*8 + h
        int r = i >> 3, h = i & 7;
        size_t li = ((size_t)bi * NH + h) * SEQ + n0 + r;
        linv[i] = 1.0f / (lbuf[li] + lbuf[LS + li]);
    }

    float acc[2][2][4] = {};

    float4 pa0[2], pa1[2], pw[2];
    #pragma unroll
    for (int p = 0; p < 2; p++) {
        int i = p * 256 + t; int r = i >> 3; int c4 = (i & 7) * 4;
        size_t ai = ((size_t)bi * SEQ + n0 + r) * CH + c4;
        pa0[p] = *(const float4*)&O0[ai];
        pa1[p] = *(const float4*)&O1[ai];
        pw[p]  = *(const float4*)&W[(size_t)(j0 + r) * CH + c4];
    }

    for (int k0 = 0; k0 < CH; k0 += 32) {
        __syncthreads();   // also orders the one-time linv writes before first use
        #pragma unroll
        for (int p = 0; p < 2; p++) {
            int i = p * 256 + t; int r = i >> 3; int c4 = (i & 7) * 4;
            float inv = linv[r * 8 + ((k0 + c4) >> 6)];
            As[r * 36 + c4 + 0] = f2tf((pa0[p].x + pa1[p].x) * inv);
            As[r * 36 + c4 + 1] = f2tf((pa0[p].y + pa1[p].y) * inv);
            As[r * 36 + c4 + 2] = f2tf((pa0[p].z + pa1[p].z) * inv);
            As[r * 36 + c4 + 3] = f2tf((pa0[p].w + pa1[p].w) * inv);
            Ws[r * 36 + c4 + 0] = f2tf(pw[p].x);
            Ws[r * 36 + c4 + 1] = f2tf(pw[p].y);
            Ws[r * 36 + c4 + 2] = f2tf(pw[p].z);
            Ws[r * 36 + c4 + 3] = f2tf(pw[p].w);
        }
        __syncthreads();
        if (k0 + 32 < CH) {
            #pragma unroll
            for (int p = 0; p < 2; p++) {
                int i = p * 256 + t; int r = i >> 3; int c4 = (i & 7) * 4;
                size_t ai = ((size_t)bi * SEQ + n0 + r) * CH + k0 + 32 + c4;
                pa0[p] = *(const float4*)&O0[ai];
                pa1[p] = *(const float4*)&O1[ai];
                pw[p]  = *(const float4*)&W[(size_t)(j0 + r) * CH + k0 + 32 + c4];
            }
        }
        #pragma unroll
        for (int ks = 0; ks < 4; ks++) {
            const int kb = ks * 8;
            uint32_t af[2][4], bf[2][2];
            #pragma unroll
            for (int mt = 0; mt < 2; mt++) {
                int m = wm * 32 + mt * 16;
                af[mt][0] = As[(m + g) * 36 + kb + tig];
                af[mt][1] = As[(m + g + 8) * 36 + kb + tig];
                af[mt][2] = As[(m + g) * 36 + kb + tig + 4];
                af[mt][3] = As[(m + g + 8) * 36 + kb + tig + 4];
            }
            #pragma unroll
            for (int nt = 0; nt < 2; nt++) {
                int n = wn * 16 + nt * 8;
                bf[nt][0] = Ws[(n + g) * 36 + kb + tig];
                bf[nt][1] = Ws[(n + g) * 36 + kb + tig + 4];
            }
            #pragma unroll
            for (int mt = 0; mt < 2; mt++)
                #pragma unroll
                for (int nt = 0; nt < 2; nt++)
                    mma8(acc[mt][nt][0], acc[mt][nt][1], acc[mt][nt][2], acc[mt][nt][3],
                         af[mt][0], af[mt][1], af[mt][2], af[mt][3],
                         bf[nt][0], bf[nt][1]);
        }
    }

    #pragma unroll
    for (int mt = 0; mt < 2; mt++) {
        int n = n0 + wm * 32 + mt * 16 + g;
        #pragma unroll
        for (int nt = 0; nt < 2; nt++) {
            int j = j0 + wn * 16 + nt * 8 + 2 * tig;
            float2 bj = *(const float2*)&bias[j];
            *(float2*)&out[((size_t)bi * SEQ + n) * CH + j] =
                make_float2(acc[mt][nt][0] + bj.x, acc[mt][nt][1] + bj.y);
            *(float2*)&out[((size_t)bi * SEQ + n + 8) * CH + j] =
                make_float2(acc[mt][nt][2] + bj.x, acc[mt][nt][3] + bj.y);
        }
    }
}

// ---------------- flash attention, 2-way K-split (R9/R14 structure, per-batch grid) -----
__global__ __launch_bounds__(256, 3) void attn_mma(
    const uint32_t* __restrict__ Q, const uint32_t* __restrict__ K,
    const uint32_t* __restrict__ V, float* __restrict__ outA,
    float* __restrict__ outB, float* __restrict__ lbuf, int bi)
{
    extern __shared__ uint32_t sm[];
    uint32_t* Qs = sm;                       // [64][68]
    uint32_t* Ks = sm + 4352;                // [64][68]
    uint32_t* Vs = sm + 8704;                // [64][72]
    uint32_t* Su = sm + 13312;               // [64][68] P (tf32 bits)
    float*    l_s = (float*)(sm + 17664);    // [64] row sums

    const int b = bi, s = blockIdx.z;
    const int h = blockIdx.y, n0 = blockIdx.x * 64;
    const int t = threadIdx.x, w = t >> 5, lane = t & 31;
    const int wm = w >> 1, wn = w & 1;
    const int g = lane >> 2, tig = lane & 3;

    const uint32_t* Qg = Q + (((size_t)b * NH + h) * SEQ + n0) * HD;
    const uint32_t* Kg = K + ((size_t)b * NH + h) * SEQ * HD;
    const uint32_t* Vg = V + ((size_t)b * NH + h) * SEQ * HD;

    #pragma unroll
    for (int p = 0; p < 4; p++) {
        int i = p * 256 + t; int r = i >> 4; int c4 = (i & 15) * 4;
        *(uint4*)&Qs[r * 68 + c4] = *(const uint4*)&Qg[(size_t)r * HD + c4];
    }
    if (t < 64) l_s[t] = 0.f;

    float acc_o[4][4];
    #pragma unroll
    for (int nt = 0; nt < 4; nt++)
        #pragma unroll
        for (int q = 0; q < 4; q++) acc_o[nt][q] = 0.f;

    const int r0 = wm * 16 + g;
    const int r1 = r0 + 8;
    const uint32_t bh = (uint32_t)(b * NH + h);
    const uint32_t base0 = ((bh << 11) + (uint32_t)(n0 + r0)) << 11;
    const uint32_t base1 = base0 + (8u << 11);
    float lr0 = 0.f, lr1 = 0.f;

    const int kbeg = s * (SEQ / 2);
    const int kend = kbeg + SEQ / 2;
    for (int k0 = kbeg; k0 < kend; k0 += 64) {
        __syncthreads();   // prev tile's mma readers done with Ks/Vs/Su
        #pragma unroll
        for (int p = 0; p < 4; p++) {
            int i = p * 256 + t; int r = i >> 4; int c4 = (i & 15) * 4;
            *(uint4*)&Ks[r * 68 + c4] = *(const uint4*)&Kg[(size_t)(k0 + r) * HD + c4];
            *(uint4*)&Vs[r * 72 + c4] = *(const uint4*)&Vg[(size_t)(k0 + r) * HD + c4];
        }
        __syncthreads();

        // --- S = Q K^T on fragments ---
        float acc_s[4][4];
        #pragma unroll
        for (int nt = 0; nt < 4; nt++)
            #pragma unroll
            for (int q = 0; q < 4; q++) acc_s[nt][q] = 0.f;
        #pragma unroll
        for (int ks = 0; ks < 8; ks++) {
            const int kb = ks * 8;
            const int m = wm * 16;
            uint32_t a0 = Qs[(m + g) * 68 + kb + tig];
            uint32_t a1 = Qs[(m + g + 8) * 68 + kb + tig];
            uint32_t a2 = Qs[(m + g) * 68 + kb + tig + 4];
            uint32_t a3 = Qs[(m + g + 8) * 68 + kb + tig + 4];
            #pragma unroll
            for (int nt = 0; nt < 4; nt++) {
                int n = wn * 32 + nt * 8;
                uint32_t b0 = Ks[(n + g) * 68 + kb + tig];
                uint32_t b1 = Ks[(n + g) * 68 + kb + tig + 4];
                mma8(acc_s[nt][0], acc_s[nt][1], acc_s[nt][2], acc_s[nt][3],
                     a0, a1, a2, a3, b0, b1);
            }
        }

        // --- fragment-space gumbel weights: w = exp2(s*SC2) * rcp(-log u) ---
        #pragma unroll
        for (int nt = 0; nt < 4; nt++) {
            const uint32_t c0 = (uint32_t)(wn * 32 + nt * 8 + 2 * tig);
            const uint32_t i00 = base0 + (uint32_t)k0 + c0;
            const uint32_t i10 = base1 + (uint32_t)k0 + c0;
            float t00 = neglog_u(tf_bits(i00));
            float t01 = neglog_u(tf_bits(i00 + 1u));
            float t10 = neglog_u(tf_bits(i10));
            float t11 = neglog_u(tf_bits(i10 + 1u));
            float w00 = ex2(acc_s[nt][0] * SC2) * frcp(t00);
            float w01 = ex2(acc_s[nt][1] * SC2) * frcp(t01);
            float w10 = ex2(acc_s[nt][2] * SC2) * frcp(t10);
            float w11 = ex2(acc_s[nt][3] * SC2) * frcp(t11);
            lr0 += w00 + w01;
            lr1 += w10 + w11;
            uint2 p0 = make_uint2(f2tf(w00), f2tf(w01));
            uint2 p1 = make_uint2(f2tf(w10), f2tf(w11));
            *(uint2*)&Su[r0 * 68 + c0] = p0;
            *(uint2*)&Su[r1 * 68 + c0] = p1;
        }
        // pair barrier: both wn halves of this wm row-group finished writing Su rows
        asm volatile("bar.sync %0, 64;" :: "r"(1 + wm) : "memory");

        // --- O += P V (A rows are this pair's own Su rows) ---
        #pragma unroll
        for (int ks = 0; ks < 8; ks++) {
            const int kb = ks * 8;
            const int m = wm * 16;
            uint32_t a0 = Su[(m + g) * 68 + kb + tig];
            uint32_t a1 = Su[(m + g + 8) * 68 + kb + tig];
            uint32_t a2 = Su[(m + g) * 68 + kb + tig + 4];
            uint32_t a3 = Su[(m + g + 8) * 68 + kb + tig + 4];
            #pragma unroll
            for (int nt = 0; nt < 4; nt++) {
                int n = wn * 32 + nt * 8;
                uint32_t b0 = Vs[(kb + tig) * 72 + n + g];
                uint32_t b1 = Vs[(kb + tig + 4) * 72 + n + g];
                mma8(acc_o[nt][0], acc_o[nt][1], acc_o[nt][2], acc_o[nt][3],
                     a0, a1, a2, a3, b0, b1);
            }
        }
    }

    // --- reduce row sums: 4 tig-lanes per row, then across wn via smem atomics ---
    lr0 += __shfl_xor_sync(0xffffffffu, lr0, 1);
    lr0 += __shfl_xor_sync(0xffffffffu, lr0, 2);
    lr1 += __shfl_xor_sync(0xffffffffu, lr1, 1);
    lr1 += __shfl_xor_sync(0xffffffffu, lr1, 2);
    if (tig == 0) {
        atomicAdd(&l_s[r0], lr0);
        atomicAdd(&l_s[r1], lr1);
    }
    __syncthreads();

    // --- epilogue: write UNNORMALIZED partials for this split ---
    float* Ob = s ? outB : outA;
    #pragma unroll
    for (int nt = 0; nt < 4; nt++) {
        int d = wn * 32 + nt * 8 + 2 * tig;
        *(float2*)&Ob[((size_t)b * SEQ + n0 + r0) * CH + h * HD + d] =
            make_float2(acc_o[nt][0], acc_o[nt][1]);
        *(float2*)&Ob[((size_t)b * SEQ + n0 + r1) * CH + h * HD + d] =
            make_float2(acc_o[nt][2], acc_o[nt][3]);
    }
    if (t < 64)
        lbuf[((size_t)s * NB * NH + bh) * SEQ + n0 + t] = l_s[t];
}

// ---------------- launch: 4 per-batch chains forked in the captured graph ---------------
extern "C" void kernel_launch(void* const* d_in, const int* in_sizes, int n_in,
                              void* d_out, int out_size)
{
    (void)in_sizes; (void)n_in; (void)out_size;
    const float* x  = (const float*)d_in[0];
    const float* y  = (const float*)d_in[1];
    const float* z  = (const float*)d_in[2];
    const float* Wq = (const float*)d_in[3];
    const float* bq = (const float*)d_in[4];
    const float* Wk = (const float*)d_in[5];
    const float* bk = (const float*)d_in[6];
    const float* Wv = (const float*)d_in[7];
    const float* bv = (const float*)d_in[8];
    const float* Wo = (const float*)d_in[9];
    const float* bo = (const float*)d_in[10];
    float* out = (float*)d_out;

    uint32_t *qp, *kp, *vp;
    float *oa, *ob, *lp;
    cudaGetSymbolAddress((void**)&qp, g_Q);
    cudaGetSymbolAddress((void**)&kp, g_K);
    cudaGetSymbolAddress((void**)&vp, g_V);
    cudaGetSymbolAddress((void**)&oa, g_oA);
    cudaGetSymbolAddress((void**)&ob, g_oB);
    cudaGetSymbolAddress((void**)&lp, g_l);

    const int SMEM = (17664 + 64) * 4;  // 70912 B -> 3 CTAs/SM
    cudaFuncSetAttribute(attn_mma, cudaFuncAttributeMaxDynamicSharedMemorySize, SMEM);

    dim3 pb(256);

    // fork from the calling (captured) stream
    cudaEventRecord(g_fork, 0);
    for (int b = 0; b < NB; b++) {
        cudaStream_t st = g_str[b];
        cudaStreamWaitEvent(st, g_fork, 0);
        proj_qkv<<<dim3(SEQ / 128, CH / 128, 3), pb, 0, st>>>(
            x, y, z, Wq, bq, Wk, bk, Wv, bv, qp, kp, vp, b);
        attn_mma<<<dim3(SEQ / 64, NH, 2), pb, SMEM, st>>>(qp, kp, vp, oa, ob, lp, b);
        proj_out64_fused<<<dim3(SEQ / 64, CH / 64, 1), pb, 0, st>>>(
            oa, ob, lp, Wo, bo, out, b);
        cudaEventRecord(g_join[b], st);
    }
    // join all chains back onto the calling stream
    for (int b = 0; b < NB; b++)
        cudaStreamWaitEvent((cudaStream_t)0, g_join[b], 0);
}